// round 14
// baseline (speedup 1.0000x reference)
#include <cuda_runtime.h>
#include <cuda_bf16.h>
#include <math.h>
#include <stdint.h>

#define DDIM 2048
#define EDIM 64
#define MTILE 64
#define KTILE 64
#define NKT (DDIM / KTILE)    // 32
#define NTHR 256
#define AMB_TH 1e-3f

// Prepped W in cp.async/LDS-friendly B-fragment order (unchanged from R9/R11):
// word P = ((((q)*128 + kcg)*4 + i)*32 + lane)*4 + c
//   q = mat*2 + split, kcg = global k16 index, uint4 i, word c
//   nt = i*2 + (c>>1), reg = c&1
//   holds bf16 pair ( W[k0][col], W[k0+1][col] ),
//   col = nt*8 + lane/4,  k0 = kcg*16 + (lane%4)*2 + 8*reg
__device__ __align__(16) uint32_t g_wb[2u * 2u * 128u * 4u * 32u * 4u];  // 1 MB

__device__ __forceinline__ uint32_t pack_bf16(__nv_bfloat16 a, __nv_bfloat16 b) {
    return (uint32_t)__bfloat16_as_ushort(a) | ((uint32_t)__bfloat16_as_ushort(b) << 16);
}

__global__ void prep_w(const float* __restrict__ Wr, const float* __restrict__ Wn) {
    int P = blockIdx.x * blockDim.x + threadIdx.x;      // 262144 words
    int c = P & 3, lane = (P >> 2) & 31, i = (P >> 7) & 3;
    int kcg = (P >> 9) & 127, split = (P >> 16) & 1, mat = P >> 17;
    const float* W = mat ? Wn : Wr;
    int nt = i * 2 + (c >> 1), reg = c & 1;
    int col = nt * 8 + (lane >> 2);
    int k0  = kcg * 16 + (lane & 3) * 2 + 8 * reg;
    float w0 = W[(size_t)k0 * EDIM + col];
    float w1 = W[(size_t)(k0 + 1) * EDIM + col];
    __nv_bfloat16 b0, b1;
    if (split == 0) {
        b0 = __float2bfloat16_rn(w0);
        b1 = __float2bfloat16_rn(w1);
    } else {
        __nv_bfloat16 h0 = __float2bfloat16_rn(w0), h1 = __float2bfloat16_rn(w1);
        b0 = __float2bfloat16_rn(w0 - __bfloat162float(h0));
        b1 = __float2bfloat16_rn(w1 - __bfloat162float(h1));
    }
    g_wb[P] = pack_bf16(b0, b1);
}

__device__ __forceinline__ void mma16816(float* d,
                                         uint32_t a0, uint32_t a1, uint32_t a2, uint32_t a3,
                                         uint32_t b0, uint32_t b1) {
    asm volatile(
        "mma.sync.aligned.m16n8k16.row.col.f32.bf16.bf16.f32 "
        "{%0,%1,%2,%3}, {%4,%5,%6,%7}, {%8,%9}, {%0,%1,%2,%3};"
        : "+f"(d[0]), "+f"(d[1]), "+f"(d[2]), "+f"(d[3])
        : "r"(a0), "r"(a1), "r"(a2), "r"(a3), "r"(b0), "r"(b1));
}

__device__ __forceinline__ void cpasync16(void* sdst, const void* gsrc) {
    unsigned int d;
    asm("{ .reg .u64 t; cvta.to.shared.u64 t, %1; cvt.u32.u64 %0, t; }" : "=r"(d) : "l"(sdst));
    asm volatile("cp.async.cg.shared.global [%0], [%1], 16;" :: "r"(d), "l"(gsrc));
}
#define CP_COMMIT() asm volatile("cp.async.commit_group;")
#define CP_WAIT0()  asm volatile("cp.async.wait_group 0;")

struct SS {
    float br[EDIM], bn[EDIM];
    float p1[MTILE], p2[MTILE];
    int   i1[MTILE], i2[MTILE];
    int   atok[MTILE];
    int4  acand[MTILE];
    int   na;
    double dot[8];
};

// dynamic smem (96KB -> 2 CTAs/SM):
//   X frag tiles [buf][split][2048 words] = 32KB  (slot S=((kc*4+tc)*32+lane)*4+reg)
//   W frag tiles [buf][q][kc][...] = 2*32KB = 64KB
// epilogue overlay: arrA (route logits 64x68) at 0, arrB (noise logits) at 32768
#define XB_OFF(b)        ((b) * 16384)
#define WB_OFF(b, q, kc) (32768 + (b) * 32768 + (q) * 8192 + (kc) * 2048)
#define DSMB 98304

__global__ __launch_bounds__(NTHR, 2) void moe_kernel(
    const float* __restrict__ X,
    const float* __restrict__ br_g, const float* __restrict__ bn_g,
    const float* __restrict__ Wr, const float* __restrict__ Wn,
    const float* __restrict__ noise,
    float* __restrict__ out_probs, float* __restrict__ out_idx, int write_idx)
{
    extern __shared__ char ds[];
    __shared__ SS ss;

    const int tid = threadIdx.x, lane = tid & 31, w = tid >> 5;  // 8 warps
    const int tc = w & 3, mat = w >> 2;                          // token chunk / matrix
    const int tokBase = blockIdx.x * MTILE;

    if (tid < EDIM) { ss.br[tid] = br_g[tid]; ss.bn[tid] = bn_g[tid]; }
    if (tid == 0) ss.na = 0;

    float acc[8][4];
#pragma unroll
    for (int nt = 0; nt < 8; nt++)
#pragma unroll
        for (int q = 0; q < 4; q++) acc[nt][q] = 0.0f;

    float2 rx[8];
    auto ldgX = [&](int t) {
#pragma unroll
        for (int j = 0; j < 8; j++) {
            int S = tid + j * NTHR;                  // 2048 slots
            int reg = S & 3, lf = (S >> 2) & 31, tcs = (S >> 7) & 3, kc = S >> 9;
            int tok = tcs * 16 + (lf >> 2) + 8 * (reg & 1);
            int kk  = kc * 16 + (lf & 3) * 2 + 8 * (reg >> 1);
            rx[j] = *reinterpret_cast<const float2*>(
                X + (size_t)(tokBase + tok) * DDIM + t * KTILE + kk);
        }
    };
    auto stsX = [&](int buf) {
#pragma unroll
        for (int j = 0; j < 8; j++) {
            int S = tid + j * NTHR;
            float2 v = rx[j];
            __nv_bfloat16 h0 = __float2bfloat16_rn(v.x), h1 = __float2bfloat16_rn(v.y);
            __nv_bfloat16 l0 = __float2bfloat16_rn(v.x - __bfloat162float(h0));
            __nv_bfloat16 l1 = __float2bfloat16_rn(v.y - __bfloat162float(h1));
            *reinterpret_cast<uint32_t*>(ds + XB_OFF(buf) + S * 4) = pack_bf16(h0, h1);
            *reinterpret_cast<uint32_t*>(ds + XB_OFF(buf) + 8192 + S * 4) = pack_bf16(l0, l1);
        }
    };
    auto cpW = [&](int t, int buf) {
#pragma unroll
        for (int j = 0; j < 8; j++) {
            int cidx = tid + j * NTHR;           // 2048 chunks of 16B
            int q = cidx >> 9, r = cidx & 511;
            cpasync16(ds + WB_OFF(buf, q, 0) + r * 16,
                      g_wb + ((size_t)(q * 128 + t * 4) * 512 + r * 4));
        }
        CP_COMMIT();
    };

    // ---- prologue: X(0) staged directly, X(1) in flight ----
    ldgX(0);
    cpW(0, 0);
    stsX(0);
    ldgX(1);

    for (int t = 0; t < NKT; t++) {
        int buf = t & 1;
        CP_WAIT0();              // W(t) landed
        __syncthreads();         // X(t), W(t) visible; compute(t-1) fully done
        if (t + 1 < NKT) cpW(t + 1, buf ^ 1);

        // ---- compute tile t (kc staggered per tc to de-convoy LDS bursts) ----
#pragma unroll
        for (int kcx = 0; kcx < 4; kcx++) {
            int kc = (kcx + tc) & 3;
            uint4 AH = *reinterpret_cast<const uint4*>(
                ds + XB_OFF(buf) + ((kc * 4 + tc) * 32 + lane) * 16);
            uint4 AL = *reinterpret_cast<const uint4*>(
                ds + XB_OFF(buf) + 8192 + ((kc * 4 + tc) * 32 + lane) * 16);
            const uint4* bhp = reinterpret_cast<const uint4*>(
                ds + WB_OFF(buf, mat * 2 + 0, kc)) + lane;
            const uint4* blp = reinterpret_cast<const uint4*>(
                ds + WB_OFF(buf, mat * 2 + 1, kc)) + lane;
            uint4 bh[4] = {bhp[0], bhp[32], bhp[64], bhp[96]};
            uint4 bl[4] = {blp[0], blp[32], blp[64], blp[96]};
            const uint32_t* bhw = reinterpret_cast<const uint32_t*>(bh);
            const uint32_t* blw = reinterpret_cast<const uint32_t*>(bl);
            // product-major order: 8 independent MMAs between any reuse of the
            // same accumulator (asm volatile pins issue order; nt-major would
            // force 3-deep same-acc dependency chains)
#pragma unroll
            for (int nt = 0; nt < 8; nt++)
                mma16816(acc[nt], AH.x, AH.y, AH.z, AH.w, bhw[nt*2], bhw[nt*2+1]); // hi*hi
#pragma unroll
            for (int nt = 0; nt < 8; nt++)
                mma16816(acc[nt], AL.x, AL.y, AL.z, AL.w, bhw[nt*2], bhw[nt*2+1]); // lo*hi
#pragma unroll
            for (int nt = 0; nt < 8; nt++)
                mma16816(acc[nt], AH.x, AH.y, AH.z, AH.w, blw[nt*2], blw[nt*2+1]); // hi*lo
        }

        // ---- stage X(t+1) off the critical path (LDG issued a tile ago) ----
        if (t + 1 < NKT) {
            stsX(buf ^ 1);       // safe: barrier(t) ended all reads of buf^1
            if (t + 2 < NKT) ldgX(t + 2);
        }
    }
    __syncthreads();   // compute done; X/W buffers reusable as logit arrays

    // ---- dump raw logits: mat0 warps -> arrA, mat1 warps -> arrB ----
    float* arrA = reinterpret_cast<float*>(ds);            // route logits [64][68]
    float* arrB = reinterpret_cast<float*>(ds + 32768);    // noise logits [64][68]
    {
        float* dst = mat ? arrB : arrA;
        int r0 = tc * 16 + (lane >> 2), r1 = r0 + 8;
        int c0 = (lane & 3) * 2;
#pragma unroll
        for (int nt = 0; nt < 8; nt++) {
            int e0 = nt * 8 + c0;
            *reinterpret_cast<float2*>(dst + r0 * 68 + e0) = make_float2(acc[nt][0], acc[nt][1]);
            *reinterpret_cast<float2*>(dst + r1 * 68 + e0) = make_float2(acc[nt][2], acc[nt][3]);
        }
    }
    __syncthreads();

    // ---- fuse bias + softplus + noise into arrA (in place) ----
#pragma unroll
    for (int j = 0; j < 16; j++) {
        int f = tid + j * NTHR;          // 4096 elements
        int tok = f >> 6, e = f & 63;
        float lr = arrA[tok * 68 + e] + ss.br[e];
        float ln = arrB[tok * 68 + e] + ss.bn[e];
        float nz = noise[(size_t)(tokBase + tok) * EDIM + e];
        // jax.nn.softplus(x) = max(x,0) + log1p(exp(-|x|))
        float sp = fmaxf(ln, 0.0f) + log1pf(expf(-fabsf(ln)));
        arrA[tok * 68 + e] = lr + nz * sp;
    }
    __syncthreads();

    // ---- top-4 scan + 2-way softmax, one thread per token ----
    if (tid < MTILE) {
        float v1 = -INFINITY, v2 = -INFINITY, v3 = -INFINITY, v4 = -INFINITY;
        int i1 = 0, i2 = 0, i3 = 0, i4 = 0;
        for (int e = 0; e < EDIM; e++) {
            float v = arrA[tid * 68 + e];
            if (v > v1)      { v4=v3; i4=i3; v3=v2; i3=i2; v2=v1; i2=i1; v1=v; i1=e; }
            else if (v > v2) { v4=v3; i4=i3; v3=v2; i3=i2; v2=v;  i2=e; }
            else if (v > v3) { v4=v3; i4=i3; v3=v;  i3=e; }
            else if (v > v4) { v4=v;  i4=e; }
        }
        float ed = expf(v2 - v1);
        float s  = 1.0f + ed;
        ss.p1[tid] = 1.0f / s;
        ss.p2[tid] = ed / s;
        ss.i1[tid] = i1;
        ss.i2[tid] = i2;
        if (write_idx) {
            out_idx[(size_t)(tokBase + tid) * 2 + 0] = (float)i1;
            out_idx[(size_t)(tokBase + tid) * 2 + 1] = (float)i2;
        }
        if ((v1 - v2) < AMB_TH || (v2 - v3) < AMB_TH) {
            int slot = atomicAdd(&ss.na, 1);
            ss.atok[slot]  = tokBase + tid;
            ss.acand[slot] = make_int4(i1, i2, i3, i4);
        }
    }
    __syncthreads();

    // ---- cooperative coalesced probs write ----
#pragma unroll
    for (int k = 0; k < 4; k++) {
        int f   = tid + k * NTHR;        // 1024 float4 stores
        int tok = f >> 4;
        int q   = f & 15;
        int i1 = ss.i1[tok], i2 = ss.i2[tok];
        float p1 = ss.p1[tok], p2 = ss.p2[tok];
        float v[4] = {0.0f, 0.0f, 0.0f, 0.0f};
        int b = q * 4;
        if (i1 >= b && i1 < b + 4) v[i1 - b] = p1;
        if (i2 >= b && i2 < b + 4) v[i2 - b] = p2;
        *reinterpret_cast<float4*>(out_probs + (size_t)(tokBase + tok) * EDIM + b) =
            make_float4(v[0], v[1], v[2], v[3]);
    }
    __syncthreads();

    // ---- fp64 arbitration for near-tie tokens (proven) ----
    int na = ss.na;
    for (int a = 0; a < na; a++) {
        int tok = ss.atok[a];
        int4 cd = ss.acand[a];
        int cand[4] = {cd.x, cd.y, cd.z, cd.w};
        if (w < 4) {
            int c = cand[w];
            const float* Xr = X + (size_t)tok * DDIM;
            double accR = 0.0, accN = 0.0;
            for (int d = lane; d < DDIM; d += 32) {
                double xv = (double)Xr[d];
                accR = fma(xv, (double)Wr[(size_t)d * EDIM + c], accR);
                accN = fma(xv, (double)Wn[(size_t)d * EDIM + c], accN);
            }
#pragma unroll
            for (int off = 16; off; off >>= 1) {
                accR += __shfl_down_sync(0xffffffffu, accR, off);
                accN += __shfl_down_sync(0xffffffffu, accN, off);
            }
            if (lane == 0) { ss.dot[w] = accR; ss.dot[4 + w] = accN; }
        }
        __syncthreads();
        if (tid == 0) {
            double nv[4];
#pragma unroll
            for (int k = 0; k < 4; k++) {
                double lg = ss.dot[k]      + (double)ss.br[cand[k]];
                double nlg = ss.dot[4 + k] + (double)ss.bn[cand[k]];
                double sp = fmax(nlg, 0.0) + log1p(exp(-fabs(nlg)));
                nv[k] = lg + (double)noise[(size_t)tok * EDIM + cand[k]] * sp;
            }
            int b1 = 0;
            for (int k = 1; k < 4; k++)
                if (nv[k] > nv[b1] || (nv[k] == nv[b1] && cand[k] < cand[b1])) b1 = k;
            int b2 = -1;
            for (int k = 0; k < 4; k++) {
                if (k == b1) continue;
                if (b2 < 0 || nv[k] > nv[b2] || (nv[k] == nv[b2] && cand[k] < cand[b2])) b2 = k;
            }
            double e = exp(nv[b2] - nv[b1]);
            double s = 1.0 + e;
            float p1 = (float)(1.0 / s), p2 = (float)(e / s);
#pragma unroll
            for (int k = 0; k < 4; k++)
                out_probs[(size_t)tok * EDIM + cand[k]] =
                    (k == b1) ? p1 : ((k == b2) ? p2 : 0.0f);
            if (write_idx) {
                out_idx[(size_t)tok * 2 + 0] = (float)cand[b1];
                out_idx[(size_t)tok * 2 + 1] = (float)cand[b2];
            }
        }
        __syncthreads();
    }
}

extern "C" void kernel_launch(void* const* d_in, const int* in_sizes, int n_in,
                              void* d_out, int out_size) {
    const float* X     = (const float*)d_in[0];   // mh_output [B,S,D]
    const float* Wr    = (const float*)d_in[1];   // W_route   [D,E]
    const float* br    = (const float*)d_in[2];   // b_route   [E]
    const float* Wn    = (const float*)d_in[3];   // W_noise   [D,E]
    const float* bn    = (const float*)d_in[4];   // b_noise   [E]
    const float* noise = (const float*)d_in[5];   // noise     [B,S,E]

    int T = in_sizes[0] / DDIM;                   // 16384 tokens
    float* out       = (float*)d_out;
    float* out_probs = out;                       // [T, E]
    float* out_idx   = out + (size_t)T * EDIM;    // [T, 2] as floats (if present)
    int write_idx = (out_size >= T * EDIM + T * 2) ? 1 : 0;

    cudaFuncSetAttribute(moe_kernel,
                         cudaFuncAttributeMaxDynamicSharedMemorySize, DSMB);
    prep_w<<<1024, 256>>>(Wr, Wn);
    moe_kernel<<<T / MTILE, NTHR, DSMB>>>(X, br, bn, Wr, Wn, noise,
                                          out_probs, out_idx, write_idx);
}

// round 15
// speedup vs baseline: 1.0215x; 1.0215x over previous
#include <cuda_runtime.h>
#include <cuda_bf16.h>
#include <math.h>
#include <stdint.h>

#define DDIM 2048
#define EDIM 64
#define MTILE 64
#define KTILE 64
#define NKT (DDIM / KTILE)    // 32
#define NTHR 512
#define AMB_TH 1e-3f

// Prepped W in cp.async/LDS-friendly B-fragment order (unchanged from R9+):
// word P = ((((q)*128 + kcg)*4 + i)*32 + lane)*4 + c
//   q = mat*2 + split, kcg = global k16 index, uint4 i, word c
//   nt = i*2 + (c>>1), reg = c&1
//   holds bf16 pair ( W[k0][col], W[k0+1][col] ),
//   col = nt*8 + lane/4,  k0 = kcg*16 + (lane%4)*2 + 8*reg
__device__ __align__(16) uint32_t g_wb[2u * 2u * 128u * 4u * 32u * 4u];  // 1 MB

__device__ __forceinline__ uint32_t pack_bf16(__nv_bfloat16 a, __nv_bfloat16 b) {
    return (uint32_t)__bfloat16_as_ushort(a) | ((uint32_t)__bfloat16_as_ushort(b) << 16);
}

__global__ void prep_w(const float* __restrict__ Wr, const float* __restrict__ Wn) {
    int P = blockIdx.x * blockDim.x + threadIdx.x;      // 262144 words
    int c = P & 3, lane = (P >> 2) & 31, i = (P >> 7) & 3;
    int kcg = (P >> 9) & 127, split = (P >> 16) & 1, mat = P >> 17;
    const float* W = mat ? Wn : Wr;
    int nt = i * 2 + (c >> 1), reg = c & 1;
    int col = nt * 8 + (lane >> 2);
    int k0  = kcg * 16 + (lane & 3) * 2 + 8 * reg;
    float w0 = W[(size_t)k0 * EDIM + col];
    float w1 = W[(size_t)(k0 + 1) * EDIM + col];
    __nv_bfloat16 b0, b1;
    if (split == 0) {
        b0 = __float2bfloat16_rn(w0);
        b1 = __float2bfloat16_rn(w1);
    } else {
        __nv_bfloat16 h0 = __float2bfloat16_rn(w0), h1 = __float2bfloat16_rn(w1);
        b0 = __float2bfloat16_rn(w0 - __bfloat162float(h0));
        b1 = __float2bfloat16_rn(w1 - __bfloat162float(h1));
    }
    g_wb[P] = pack_bf16(b0, b1);
}

__device__ __forceinline__ void mma16816(float* d,
                                         uint32_t a0, uint32_t a1, uint32_t a2, uint32_t a3,
                                         uint32_t b0, uint32_t b1) {
    asm volatile(
        "mma.sync.aligned.m16n8k16.row.col.f32.bf16.bf16.f32 "
        "{%0,%1,%2,%3}, {%4,%5,%6,%7}, {%8,%9}, {%0,%1,%2,%3};"
        : "+f"(d[0]), "+f"(d[1]), "+f"(d[2]), "+f"(d[3])
        : "r"(a0), "r"(a1), "r"(a2), "r"(a3), "r"(b0), "r"(b1));
}

__device__ __forceinline__ void cpasync16(void* sdst, const void* gsrc) {
    unsigned int d;
    asm("{ .reg .u64 t; cvta.to.shared.u64 t, %1; cvt.u32.u64 %0, t; }" : "=r"(d) : "l"(sdst));
    asm volatile("cp.async.cg.shared.global [%0], [%1], 16;" :: "r"(d), "l"(gsrc));
}
#define CP_COMMIT() asm volatile("cp.async.commit_group;")
#define CP_WAIT0()  asm volatile("cp.async.wait_group 0;")

struct SS {
    float br[EDIM], bn[EDIM];
    float p1[MTILE], p2[MTILE];
    int   i1[MTILE], i2[MTILE];
    int   atok[MTILE];
    int4  acand[MTILE];
    int   na;
    double dot[8];
};

// dynamic smem (96KB -> 2 CTAs/SM):
//   X frag tiles [buf][split][2048 words] = 32KB  (slot S=((kc*4+tc)*32+lane)*4+reg)
//   W frag tiles [buf][q][kc][...] = 2*32KB = 64KB
// epilogue overlay: arrA (route logits 64x68) at 0, arrB (noise logits) at 32768
#define XB_OFF(b)        ((b) * 16384)
#define WB_OFF(b, q, kc) (32768 + (b) * 32768 + (q) * 8192 + (kc) * 2048)
#define DSMB 98304

__global__ __launch_bounds__(NTHR, 2) void moe_kernel(
    const float* __restrict__ X,
    const float* __restrict__ br_g, const float* __restrict__ bn_g,
    const float* __restrict__ Wr, const float* __restrict__ Wn,
    const float* __restrict__ noise,
    float* __restrict__ out_probs, float* __restrict__ out_idx, int write_idx)
{
    extern __shared__ char ds[];
    __shared__ SS ss;

    const int tid = threadIdx.x, lane = tid & 31, w = tid >> 5;  // 16 warps
    const int tc  = w & 3;             // token chunk 0..3
    const int nth = (w >> 2) & 1;      // column half: nt = nth*4 + 0..3
    const int mat = w >> 3;            // 0 = route, 1 = noise
    const int tokBase = blockIdx.x * MTILE;

    if (tid < EDIM) { ss.br[tid] = br_g[tid]; ss.bn[tid] = bn_g[tid]; }
    if (tid == 0) ss.na = 0;

    float acc[4][4];
#pragma unroll
    for (int nt = 0; nt < 4; nt++)
#pragma unroll
        for (int q = 0; q < 4; q++) acc[nt][q] = 0.0f;

    float2 rx[4];
    auto ldgX = [&](int t) {
#pragma unroll
        for (int j = 0; j < 4; j++) {
            int S = tid + j * NTHR;                  // 2048 slots
            int reg = S & 3, lf = (S >> 2) & 31, tcs = (S >> 7) & 3, kc = S >> 9;
            int tok = tcs * 16 + (lf >> 2) + 8 * (reg & 1);
            int kk  = kc * 16 + (lf & 3) * 2 + 8 * (reg >> 1);
            rx[j] = *reinterpret_cast<const float2*>(
                X + (size_t)(tokBase + tok) * DDIM + t * KTILE + kk);
        }
    };
    auto stsX = [&](int buf) {
#pragma unroll
        for (int j = 0; j < 4; j++) {
            int S = tid + j * NTHR;
            float2 v = rx[j];
            __nv_bfloat16 h0 = __float2bfloat16_rn(v.x), h1 = __float2bfloat16_rn(v.y);
            __nv_bfloat16 l0 = __float2bfloat16_rn(v.x - __bfloat162float(h0));
            __nv_bfloat16 l1 = __float2bfloat16_rn(v.y - __bfloat162float(h1));
            *reinterpret_cast<uint32_t*>(ds + XB_OFF(buf) + S * 4) = pack_bf16(h0, h1);
            *reinterpret_cast<uint32_t*>(ds + XB_OFF(buf) + 8192 + S * 4) = pack_bf16(l0, l1);
        }
    };
    auto cpW = [&](int t, int buf) {
#pragma unroll
        for (int j = 0; j < 4; j++) {
            int cidx = tid + j * NTHR;           // 2048 chunks of 16B
            int q = cidx >> 9, r = cidx & 511;
            cpasync16(ds + WB_OFF(buf, q, 0) + r * 16,
                      g_wb + ((size_t)(q * 128 + t * 4) * 512 + r * 4));
        }
        CP_COMMIT();
    };

    // ---- prologue: X(0) staged directly, X(1) in flight ----
    ldgX(0);
    cpW(0, 0);
    stsX(0);
    ldgX(1);

    for (int t = 0; t < NKT; t++) {
        int buf = t & 1;
        CP_WAIT0();              // W(t) landed
        __syncthreads();         // X(t), W(t) visible; compute(t-1) fully done
        if (t + 1 < NKT) cpW(t + 1, buf ^ 1);

        // ---- compute tile t (kc staggered per tc) ----
#pragma unroll
        for (int kcx = 0; kcx < 4; kcx++) {
            int kc = (kcx + tc) & 3;
            uint4 AH = *reinterpret_cast<const uint4*>(
                ds + XB_OFF(buf) + ((kc * 4 + tc) * 32 + lane) * 16);
            uint4 AL = *reinterpret_cast<const uint4*>(
                ds + XB_OFF(buf) + 8192 + ((kc * 4 + tc) * 32 + lane) * 16);
            const uint4* bhp = reinterpret_cast<const uint4*>(
                ds + WB_OFF(buf, mat * 2 + 0, kc));
            const uint4* blp = reinterpret_cast<const uint4*>(
                ds + WB_OFF(buf, mat * 2 + 1, kc));
            // this warp's 4 nt tiles live in uint4 rows i = nth*2, nth*2+1
            uint4 bh[2] = { bhp[nth * 64 + lane], bhp[nth * 64 + 32 + lane] };
            uint4 bl[2] = { blp[nth * 64 + lane], blp[nth * 64 + 32 + lane] };
            const uint32_t* bhw = reinterpret_cast<const uint32_t*>(bh);
            const uint32_t* blw = reinterpret_cast<const uint32_t*>(bl);
#pragma unroll
            for (int nt = 0; nt < 4; nt++)
                mma16816(acc[nt], AH.x, AH.y, AH.z, AH.w, bhw[nt*2], bhw[nt*2+1]); // hi*hi
#pragma unroll
            for (int nt = 0; nt < 4; nt++)
                mma16816(acc[nt], AL.x, AL.y, AL.z, AL.w, bhw[nt*2], bhw[nt*2+1]); // lo*hi
#pragma unroll
            for (int nt = 0; nt < 4; nt++)
                mma16816(acc[nt], AH.x, AH.y, AH.z, AH.w, blw[nt*2], blw[nt*2+1]); // hi*lo
        }

        // ---- stage X(t+1) off the critical path (LDG issued a tile ago) ----
        if (t + 1 < NKT) {
            stsX(buf ^ 1);       // safe: barrier(t) ended all reads of buf^1
            if (t + 2 < NKT) ldgX(t + 2);
        }
    }
    __syncthreads();   // compute done; X/W buffers reusable as logit arrays

    // ---- dump raw logits: mat0 warps -> arrA, mat1 warps -> arrB ----
    float* arrA = reinterpret_cast<float*>(ds);            // route logits [64][68]
    float* arrB = reinterpret_cast<float*>(ds + 32768);    // noise logits [64][68]
    {
        float* dst = mat ? arrB : arrA;
        int r0 = tc * 16 + (lane >> 2), r1 = r0 + 8;
        int c0 = (lane & 3) * 2;
#pragma unroll
        for (int nt = 0; nt < 4; nt++) {
            int e0 = (nth * 4 + nt) * 8 + c0;
            *reinterpret_cast<float2*>(dst + r0 * 68 + e0) = make_float2(acc[nt][0], acc[nt][1]);
            *reinterpret_cast<float2*>(dst + r1 * 68 + e0) = make_float2(acc[nt][2], acc[nt][3]);
        }
    }
    __syncthreads();

    // ---- fuse bias + softplus + noise into arrA (in place) ----
#pragma unroll
    for (int j = 0; j < 8; j++) {
        int f = tid + j * NTHR;          // 4096 elements
        int tok = f >> 6, e = f & 63;
        float lr = arrA[tok * 68 + e] + ss.br[e];
        float ln = arrB[tok * 68 + e] + ss.bn[e];
        float nz = noise[(size_t)(tokBase + tok) * EDIM + e];
        // jax.nn.softplus(x) = max(x,0) + log1p(exp(-|x|))
        float sp = fmaxf(ln, 0.0f) + log1pf(expf(-fabsf(ln)));
        arrA[tok * 68 + e] = lr + nz * sp;
    }
    __syncthreads();

    // ---- top-4 scan + 2-way softmax, one thread per token ----
    if (tid < MTILE) {
        float v1 = -INFINITY, v2 = -INFINITY, v3 = -INFINITY, v4 = -INFINITY;
        int i1 = 0, i2 = 0, i3 = 0, i4 = 0;
        for (int e = 0; e < EDIM; e++) {
            float v = arrA[tid * 68 + e];
            if (v > v1)      { v4=v3; i4=i3; v3=v2; i3=i2; v2=v1; i2=i1; v1=v; i1=e; }
            else if (v > v2) { v4=v3; i4=i3; v3=v2; i3=i2; v2=v;  i2=e; }
            else if (v > v3) { v4=v3; i4=i3; v3=v;  i3=e; }
            else if (v > v4) { v4=v;  i4=e; }
        }
        float ed = expf(v2 - v1);
        float s  = 1.0f + ed;
        ss.p1[tid] = 1.0f / s;
        ss.p2[tid] = ed / s;
        ss.i1[tid] = i1;
        ss.i2[tid] = i2;
        if (write_idx) {
            out_idx[(size_t)(tokBase + tid) * 2 + 0] = (float)i1;
            out_idx[(size_t)(tokBase + tid) * 2 + 1] = (float)i2;
        }
        if ((v1 - v2) < AMB_TH || (v2 - v3) < AMB_TH) {
            int slot = atomicAdd(&ss.na, 1);
            ss.atok[slot]  = tokBase + tid;
            ss.acand[slot] = make_int4(i1, i2, i3, i4);
        }
    }
    __syncthreads();

    // ---- cooperative coalesced probs write ----
#pragma unroll
    for (int k = 0; k < 2; k++) {
        int f   = tid + k * NTHR;        // 1024 float4 stores
        int tok = f >> 4;
        int q   = f & 15;
        int i1 = ss.i1[tok], i2 = ss.i2[tok];
        float p1 = ss.p1[tok], p2 = ss.p2[tok];
        float v[4] = {0.0f, 0.0f, 0.0f, 0.0f};
        int b = q * 4;
        if (i1 >= b && i1 < b + 4) v[i1 - b] = p1;
        if (i2 >= b && i2 < b + 4) v[i2 - b] = p2;
        *reinterpret_cast<float4*>(out_probs + (size_t)(tokBase + tok) * EDIM + b) =
            make_float4(v[0], v[1], v[2], v[3]);
    }
    __syncthreads();

    // ---- fp64 arbitration for near-tie tokens (proven) ----
    int na = ss.na;
    for (int a = 0; a < na; a++) {
        int tok = ss.atok[a];
        int4 cd = ss.acand[a];
        int cand[4] = {cd.x, cd.y, cd.z, cd.w};
        if (w < 4) {
            int c = cand[w];
            const float* Xr = X + (size_t)tok * DDIM;
            double accR = 0.0, accN = 0.0;
            for (int d = lane; d < DDIM; d += 32) {
                double xv = (double)Xr[d];
                accR = fma(xv, (double)Wr[(size_t)d * EDIM + c], accR);
                accN = fma(xv, (double)Wn[(size_t)d * EDIM + c], accN);
            }
#pragma unroll
            for (int off = 16; off; off >>= 1) {
                accR += __shfl_down_sync(0xffffffffu, accR, off);
                accN += __shfl_down_sync(0xffffffffu, accN, off);
            }
            if (lane == 0) { ss.dot[w] = accR; ss.dot[4 + w] = accN; }
        }
        __syncthreads();
        if (tid == 0) {
            double nv[4];
#pragma unroll
            for (int k = 0; k < 4; k++) {
                double lg = ss.dot[k]      + (double)ss.br[cand[k]];
                double nlg = ss.dot[4 + k] + (double)ss.bn[cand[k]];
                double sp = fmax(nlg, 0.0) + log1p(exp(-fabs(nlg)));
                nv[k] = lg + (double)noise[(size_t)tok * EDIM + cand[k]] * sp;
            }
            int b1 = 0;
            for (int k = 1; k < 4; k++)
                if (nv[k] > nv[b1] || (nv[k] == nv[b1] && cand[k] < cand[b1])) b1 = k;
            int b2 = -1;
            for (int k = 0; k < 4; k++) {
                if (k == b1) continue;
                if (b2 < 0 || nv[k] > nv[b2] || (nv[k] == nv[b2] && cand[k] < cand[b2])) b2 = k;
            }
            double e = exp(nv[b2] - nv[b1]);
            double s = 1.0 + e;
            float p1 = (float)(1.0 / s), p2 = (float)(e / s);
#pragma unroll
            for (int k = 0; k < 4; k++)
                out_probs[(size_t)tok * EDIM + cand[k]] =
                    (k == b1) ? p1 : ((k == b2) ? p2 : 0.0f);
            if (write_idx) {
                out_idx[(size_t)tok * 2 + 0] = (float)cand[b1];
                out_idx[(size_t)tok * 2 + 1] = (float)cand[b2];
            }
        }
        __syncthreads();
    }
}

extern "C" void kernel_launch(void* const* d_in, const int* in_sizes, int n_in,
                              void* d_out, int out_size) {
    const float* X     = (const float*)d_in[0];   // mh_output [B,S,D]
    const float* Wr    = (const float*)d_in[1];   // W_route   [D,E]
    const float* br    = (const float*)d_in[2];   // b_route   [E]
    const float* Wn    = (const float*)d_in[3];   // W_noise   [D,E]
    const float* bn    = (const float*)d_in[4];   // b_noise   [E]
    const float* noise = (const float*)d_in[5];   // noise     [B,S,E]

    int T = in_sizes[0] / DDIM;                   // 16384 tokens
    float* out       = (float*)d_out;
    float* out_probs = out;                       // [T, E]
    float* out_idx   = out + (size_t)T * EDIM;    // [T, 2] as floats (if present)
    int write_idx = (out_size >= T * EDIM + T * 2) ? 1 : 0;

    cudaFuncSetAttribute(moe_kernel,
                         cudaFuncAttributeMaxDynamicSharedMemorySize, DSMB);
    prep_w<<<1024, 256>>>(Wr, Wn);
    moe_kernel<<<T / MTILE, NTHR, DSMB>>>(X, br, bn, Wr, Wn, noise,
                                          out_probs, out_idx, write_idx);
}